// round 5
// baseline (speedup 1.0000x reference)
#include <cuda_runtime.h>

// GEMV: y = alpha * (A @ x) + beta * b
// Persistent grid-stride: one wave of 888 CTAs (6/SM), each handles ~4.6
// groups of 4 rows. x becomes L1-resident after first group; no wave
// transitions; no late-CTA L1tex-queue spread across waves.

#define ROWS 16384
#define COLS 16384
#define TPB  256
#define RPB  4
#define NGROUPS (ROWS / RPB)
#define NBLOCKS (148 * 6)

__global__ __launch_bounds__(TPB) void gemv_kernel(
    const float* __restrict__ alpha,
    const float* __restrict__ A,
    const float* __restrict__ x,
    const float* __restrict__ beta,
    const float* __restrict__ b,
    float* __restrict__ y)
{
    const int tid  = threadIdx.x;
    const int lane = tid & 31;
    const int wid  = tid >> 5;
    const float4* __restrict__ xv = reinterpret_cast<const float4*>(x);

    __shared__ float warp_sums[RPB][TPB / 32];

    for (int g = blockIdx.x; g < NGROUPS; g += gridDim.x) {
        const int row0 = g * RPB;
        const float4* __restrict__ r0 = reinterpret_cast<const float4*>(A + (size_t)(row0 + 0) * COLS);
        const float4* __restrict__ r1 = reinterpret_cast<const float4*>(A + (size_t)(row0 + 1) * COLS);
        const float4* __restrict__ r2 = reinterpret_cast<const float4*>(A + (size_t)(row0 + 2) * COLS);
        const float4* __restrict__ r3 = reinterpret_cast<const float4*>(A + (size_t)(row0 + 3) * COLS);

        float acc0 = 0.0f, acc1 = 0.0f, acc2 = 0.0f, acc3 = 0.0f;

        #pragma unroll 4
        for (int i = tid; i < COLS / 4; i += TPB) {
            float4 a0 = __ldcs(&r0[i]);
            float4 a1 = __ldcs(&r1[i]);
            float4 a2 = __ldcs(&r2[i]);
            float4 a3 = __ldcs(&r3[i]);
            float4 v  = __ldg(&xv[i]);   // L1-resident after first group
            acc0 = fmaf(a0.x, v.x, acc0); acc0 = fmaf(a0.y, v.y, acc0);
            acc0 = fmaf(a0.z, v.z, acc0); acc0 = fmaf(a0.w, v.w, acc0);
            acc1 = fmaf(a1.x, v.x, acc1); acc1 = fmaf(a1.y, v.y, acc1);
            acc1 = fmaf(a1.z, v.z, acc1); acc1 = fmaf(a1.w, v.w, acc1);
            acc2 = fmaf(a2.x, v.x, acc2); acc2 = fmaf(a2.y, v.y, acc2);
            acc2 = fmaf(a2.z, v.z, acc2); acc2 = fmaf(a2.w, v.w, acc2);
            acc3 = fmaf(a3.x, v.x, acc3); acc3 = fmaf(a3.y, v.y, acc3);
            acc3 = fmaf(a3.z, v.z, acc3); acc3 = fmaf(a3.w, v.w, acc3);
        }

        #pragma unroll
        for (int off = 16; off > 0; off >>= 1) {
            acc0 += __shfl_xor_sync(0xFFFFFFFFu, acc0, off);
            acc1 += __shfl_xor_sync(0xFFFFFFFFu, acc1, off);
            acc2 += __shfl_xor_sync(0xFFFFFFFFu, acc2, off);
            acc3 += __shfl_xor_sync(0xFFFFFFFFu, acc3, off);
        }

        if (lane == 0) {
            warp_sums[0][wid] = acc0;
            warp_sums[1][wid] = acc1;
            warp_sums[2][wid] = acc2;
            warp_sums[3][wid] = acc3;
        }
        __syncthreads();

        if (wid == 0 && lane < RPB * (TPB / 32)) {
            const int r = lane >> 3;
            const int w = lane & 7;
            float s = warp_sums[r][w];
            #pragma unroll
            for (int off = 4; off > 0; off >>= 1)
                s += __shfl_xor_sync(0xFFFFFFFFu, s, off);
            if (w == 0)
                y[row0 + r] = alpha[0] * s + beta[0] * b[row0 + r];
        }
        __syncthreads();   // protect warp_sums reuse next group
    }
}

extern "C" void kernel_launch(void* const* d_in, const int* in_sizes, int n_in,
                              void* d_out, int out_size) {
    const float* alpha = (const float*)d_in[0];
    const float* A     = (const float*)d_in[1];
    const float* x     = (const float*)d_in[2];
    const float* beta  = (const float*)d_in[3];
    const float* b     = (const float*)d_in[4];
    float* y = (float*)d_out;

    gemv_kernel<<<NBLOCKS, TPB>>>(alpha, A, x, beta, b, y);
}

// round 6
// speedup vs baseline: 1.1057x; 1.1057x over previous
#include <cuda_runtime.h>

// GEMV: y = alpha * (A @ x) + beta * b
// A: [16384,16384] f32. Occupancy-max variant: launch_bounds(256,8) forces
// <=32 regs -> 8 CTAs/SM (100% occ) -> more outstanding LDGs -> higher DRAM%.
// RPB=2 rows/CTA keeps reg pressure low while halving x L2 traffic.

#define ROWS 16384
#define COLS 16384
#define TPB  256
#define RPB  2

__global__ __launch_bounds__(TPB, 8) void gemv_kernel(
    const float* __restrict__ alpha,
    const float* __restrict__ A,
    const float* __restrict__ x,
    const float* __restrict__ beta,
    const float* __restrict__ b,
    float* __restrict__ y)
{
    const int row0 = blockIdx.x * RPB;
    const int tid  = threadIdx.x;

    const float4* __restrict__ r0 = reinterpret_cast<const float4*>(A + (size_t)row0 * COLS);
    const float4* __restrict__ r1 = reinterpret_cast<const float4*>(A + (size_t)(row0 + 1) * COLS);
    const float4* __restrict__ xv = reinterpret_cast<const float4*>(x);

    float acc0 = 0.0f, acc1 = 0.0f;

    // COLS/4 = 4096 float4; 256 threads -> 16 iterations each.
    #pragma unroll 2
    for (int i = tid; i < COLS / 4; i += TPB) {
        float4 a0 = __ldcs(&r0[i]);
        float4 a1 = __ldcs(&r1[i]);
        float4 v  = __ldg(&xv[i]);
        acc0 = fmaf(a0.x, v.x, acc0); acc0 = fmaf(a0.y, v.y, acc0);
        acc0 = fmaf(a0.z, v.z, acc0); acc0 = fmaf(a0.w, v.w, acc0);
        acc1 = fmaf(a1.x, v.x, acc1); acc1 = fmaf(a1.y, v.y, acc1);
        acc1 = fmaf(a1.z, v.z, acc1); acc1 = fmaf(a1.w, v.w, acc1);
    }

    // warp reduce both accumulators
    #pragma unroll
    for (int off = 16; off > 0; off >>= 1) {
        acc0 += __shfl_xor_sync(0xFFFFFFFFu, acc0, off);
        acc1 += __shfl_xor_sync(0xFFFFFFFFu, acc1, off);
    }

    __shared__ float warp_sums[RPB][TPB / 32];
    const int lane = tid & 31;
    const int wid  = tid >> 5;
    if (lane == 0) {
        warp_sums[0][wid] = acc0;
        warp_sums[1][wid] = acc1;
    }
    __syncthreads();

    // warp 0: lanes 0..15 cover 2 rows x 8 warp-sums
    if (wid == 0 && lane < RPB * (TPB / 32)) {
        const int r = lane >> 3;
        const int w = lane & 7;
        float s = warp_sums[r][w];
        #pragma unroll
        for (int off = 4; off > 0; off >>= 1)
            s += __shfl_xor_sync(0xFFFFFFFFu, s, off);
        if (w == 0)
            y[row0 + r] = alpha[0] * s + beta[0] * b[row0 + r];
    }
}

extern "C" void kernel_launch(void* const* d_in, const int* in_sizes, int n_in,
                              void* d_out, int out_size) {
    const float* alpha = (const float*)d_in[0];
    const float* A     = (const float*)d_in[1];
    const float* x     = (const float*)d_in[2];
    const float* beta  = (const float*)d_in[3];
    const float* b     = (const float*)d_in[4];
    float* y = (float*)d_out;

    gemv_kernel<<<ROWS / RPB, TPB>>>(alpha, A, x, beta, b, y);
}